// round 1
// baseline (speedup 1.0000x reference)
#include <cuda_runtime.h>
#include <math.h>

#define HID   4096
#define BOT   64
#define RDIM  48
#define NSLOT 1024
#define TOPK  8
#define VB    256
#define MAXTOK 4096

// ---------------- scratch (device globals; no allocations allowed) ----------
__device__ float g_q[MAXTOK * BOT];       // h @ Wq^T
__device__ float g_rk[NSLOT * RDIM];      // aux_keys @ Wr^T
__device__ float g_AV[NSLOT * VB];        // aux_values @ Wvd^T (folded bottleneck)
__device__ float g_logvar[MAXTOK];
__device__ float g_learned[MAXTOK];       // sum gelu(h@Wu1^T+bu1)*Wu2 (pre-bu2)
__device__ float g_t[MAXTOK * VB];        // per-token bottleneck vector
__device__ float g_meanlv;

__device__ __forceinline__ float gelu_tanh(float x) {
    float x3 = x * x * x;
    float t = tanhf(0.7978845608028654f * (x + 0.044715f * x3));
    return 0.5f * x * (1.0f + t);
}
__device__ __forceinline__ float sigmoidf(float x) {
    return 1.0f / (1.0f + expf(-x));
}

// ---------------- tiny init ----------------
__global__ void k_zero(int M) {
    int i = blockIdx.x * 256 + threadIdx.x;
    if (i < M) g_learned[i] = 0.0f;
}

// ---------------- rk = aux_keys @ Wr^T  [NSLOT, RDIM] ----------------
__global__ void k_rk(const float* __restrict__ aux_keys, const float* __restrict__ Wr) {
    __shared__ float kr[BOT];
    int n = blockIdx.x, tid = threadIdx.x;
    if (tid < BOT) kr[tid] = aux_keys[n * BOT + tid];
    __syncthreads();
    if (tid < RDIM) {
        float a = 0.f;
        #pragma unroll
        for (int j = 0; j < BOT; j++) a += kr[j] * Wr[tid * BOT + j];
        g_rk[n * RDIM + tid] = a;
    }
}

// ============ shared 64x64x16 fp32 GEMM tile pattern (A[M,K] * B[N,K]^T) ====
// 256 threads, 4x4 microtile, smem stride 68 (bank-safe, float4-aligned).

// ---------------- AV = aux_values @ Wvd^T  [NSLOT, VB] ----------------
__global__ __launch_bounds__(256) void k_av(const float* __restrict__ A,
                                            const float* __restrict__ Bm) {
    __shared__ float As[16][68];
    __shared__ float Bs[16][68];
    int tid = threadIdx.x, tx = tid & 15, ty = tid >> 4;
    int m0 = blockIdx.y * 64, n0 = blockIdx.x * 64;
    int lr = tid >> 2, lk = (tid & 3) << 2;
    const float* ap = A + (size_t)(m0 + lr) * HID + lk;
    const float* bp = Bm + (size_t)(n0 + lr) * HID + lk;
    float acc[4][4] = {};
    for (int k0 = 0; k0 < HID; k0 += 16) {
        float4 a4 = *(const float4*)(ap + k0);
        float4 b4 = *(const float4*)(bp + k0);
        As[lk + 0][lr] = a4.x; As[lk + 1][lr] = a4.y; As[lk + 2][lr] = a4.z; As[lk + 3][lr] = a4.w;
        Bs[lk + 0][lr] = b4.x; Bs[lk + 1][lr] = b4.y; Bs[lk + 2][lr] = b4.z; Bs[lk + 3][lr] = b4.w;
        __syncthreads();
        #pragma unroll
        for (int k = 0; k < 16; k++) {
            float4 av = *(const float4*)&As[k][ty << 2];
            float4 bv = *(const float4*)&Bs[k][tx << 2];
            float am[4] = {av.x, av.y, av.z, av.w};
            float bn[4] = {bv.x, bv.y, bv.z, bv.w};
            #pragma unroll
            for (int i = 0; i < 4; i++)
                #pragma unroll
                for (int j = 0; j < 4; j++) acc[i][j] += am[i] * bn[j];
        }
        __syncthreads();
    }
    #pragma unroll
    for (int i = 0; i < 4; i++) {
        float4 o = make_float4(acc[i][0], acc[i][1], acc[i][2], acc[i][3]);
        *(float4*)&g_AV[(size_t)(m0 + (ty << 2) + i) * VB + n0 + (tx << 2)] = o;
    }
}

// ---------------- q = h @ Wq^T [M,64], fused per-token var stats ------------
__global__ __launch_bounds__(256) void k_qvar(const float* __restrict__ A,
                                              const float* __restrict__ Bm) {
    __shared__ float As[16][68];
    __shared__ float Bs[16][68];
    int tid = threadIdx.x, tx = tid & 15, ty = tid >> 4;
    int m0 = blockIdx.x * 64;
    int lr = tid >> 2, lk = (tid & 3) << 2;
    const float* ap = A + (size_t)(m0 + lr) * HID + lk;
    const float* bp = Bm + (size_t)lr * HID + lk;   // Wq rows 0..63
    float acc[4][4] = {};
    float rs = 0.f, rs2 = 0.f;
    for (int k0 = 0; k0 < HID; k0 += 16) {
        float4 a4 = *(const float4*)(ap + k0);
        float4 b4 = *(const float4*)(bp + k0);
        As[lk + 0][lr] = a4.x; As[lk + 1][lr] = a4.y; As[lk + 2][lr] = a4.z; As[lk + 3][lr] = a4.w;
        Bs[lk + 0][lr] = b4.x; Bs[lk + 1][lr] = b4.y; Bs[lk + 2][lr] = b4.z; Bs[lk + 3][lr] = b4.w;
        __syncthreads();
        if (tid < 64) {
            #pragma unroll
            for (int k = 0; k < 16; k++) { float v = As[k][tid]; rs += v; rs2 += v * v; }
        }
        #pragma unroll
        for (int k = 0; k < 16; k++) {
            float4 av = *(const float4*)&As[k][ty << 2];
            float4 bv = *(const float4*)&Bs[k][tx << 2];
            float am[4] = {av.x, av.y, av.z, av.w};
            float bn[4] = {bv.x, bv.y, bv.z, bv.w};
            #pragma unroll
            for (int i = 0; i < 4; i++)
                #pragma unroll
                for (int j = 0; j < 4; j++) acc[i][j] += am[i] * bn[j];
        }
        __syncthreads();
    }
    #pragma unroll
    for (int i = 0; i < 4; i++) {
        float4 o = make_float4(acc[i][0], acc[i][1], acc[i][2], acc[i][3]);
        *(float4*)&g_q[(size_t)(m0 + (ty << 2) + i) * BOT + (tx << 2)] = o;
    }
    if (tid < 64) {
        float mean = rs * (1.0f / HID);
        float var = rs2 * (1.0f / HID) - mean * mean;
        g_logvar[m0 + tid] = log1pf(var);
    }
}

// ---------------- learned partial: sum_n gelu(h@Wu1^T + bu1)*Wu2 ------------
__global__ __launch_bounds__(256) void k_learned(const float* __restrict__ A,
                                                 const float* __restrict__ Bm,
                                                 const float* __restrict__ bu1,
                                                 const float* __restrict__ Wu2) {
    __shared__ float As[16][68];
    __shared__ float Bs[16][68];
    __shared__ float red[64][17];
    int tid = threadIdx.x, tx = tid & 15, ty = tid >> 4;
    int m0 = blockIdx.y * 64, n0 = blockIdx.x * 64;
    int lr = tid >> 2, lk = (tid & 3) << 2;
    const float* ap = A + (size_t)(m0 + lr) * HID + lk;
    const float* bp = Bm + (size_t)(n0 + lr) * HID + lk;
    float acc[4][4] = {};
    for (int k0 = 0; k0 < HID; k0 += 16) {
        float4 a4 = *(const float4*)(ap + k0);
        float4 b4 = *(const float4*)(bp + k0);
        As[lk + 0][lr] = a4.x; As[lk + 1][lr] = a4.y; As[lk + 2][lr] = a4.z; As[lk + 3][lr] = a4.w;
        Bs[lk + 0][lr] = b4.x; Bs[lk + 1][lr] = b4.y; Bs[lk + 2][lr] = b4.z; Bs[lk + 3][lr] = b4.w;
        __syncthreads();
        #pragma unroll
        for (int k = 0; k < 16; k++) {
            float4 av = *(const float4*)&As[k][ty << 2];
            float4 bv = *(const float4*)&Bs[k][tx << 2];
            float am[4] = {av.x, av.y, av.z, av.w};
            float bn[4] = {bv.x, bv.y, bv.z, bv.w};
            #pragma unroll
            for (int i = 0; i < 4; i++)
                #pragma unroll
                for (int j = 0; j < 4; j++) acc[i][j] += am[i] * bn[j];
        }
        __syncthreads();
    }
    #pragma unroll
    for (int i = 0; i < 4; i++) {
        float p = 0.f;
        #pragma unroll
        for (int j = 0; j < 4; j++) {
            int n = n0 + (tx << 2) + j;
            float x = acc[i][j] + bu1[n];
            p += gelu_tanh(x) * Wu2[n];
        }
        red[(ty << 2) + i][tx] = p;
    }
    __syncthreads();
    if (tid < 64) {
        float s = 0.f;
        #pragma unroll
        for (int t = 0; t < 16; t++) s += red[tid][t];
        atomicAdd(&g_learned[m0 + tid], s);
    }
}

// ---------------- mean(log_var) over tokens (deterministic tree) ------------
__global__ void k_mean(int M) {
    __shared__ float s[256];
    int tid = threadIdx.x;
    float a = 0.f;
    for (int i = tid; i < M; i += 256) a += g_logvar[i];
    s[tid] = a; __syncthreads();
    for (int st = 128; st > 0; st >>= 1) {
        if (tid < st) s[tid] += s[tid + st];
        __syncthreads();
    }
    if (tid == 0) g_meanlv = s[0] / (float)M;
}

// ------- router: scores, top-8, softmax attn, t = sum w*AV[idx] (per token) -
__global__ __launch_bounds__(256) void k_router(const float* __restrict__ aux_keys,
                                                const float* __restrict__ Wr,
                                                const float* __restrict__ log_rel) {
    __shared__ float s_q[BOT];
    __shared__ float s_rq[RDIM];
    __shared__ float s_scores[NSLOT];
    __shared__ float s_rv[256];
    __shared__ int   s_ri[256];
    __shared__ int   s_idx[TOPK];
    __shared__ float s_w[TOPK];
    __shared__ float s_attn[TOPK];

    int tok = blockIdx.x, tid = threadIdx.x;
    if (tid < BOT) s_q[tid] = g_q[(size_t)tok * BOT + tid];
    __syncthreads();
    if (tid < RDIM) {
        float a = 0.f;
        #pragma unroll
        for (int j = 0; j < BOT; j++) a += s_q[j] * Wr[tid * BOT + j];
        s_rq[tid] = a;
    }
    __syncthreads();
    const float inv_sqrt_rdim = 0.14433756729740643f;   // 1/sqrt(48)
    for (int n = tid; n < NSLOT; n += 256) {
        float a = 0.f;
        #pragma unroll
        for (int r = 0; r < RDIM; r++) a += s_rq[r] * g_rk[n * RDIM + r];
        s_scores[n] = a * inv_sqrt_rdim + log_rel[n];
    }
    __syncthreads();
    // top-8 by repeated argmax (min-index tie-break)
    for (int kk = 0; kk < TOPK; kk++) {
        float bv = -INFINITY; int bi = 0x7FFFFFFF;
        for (int n = tid; n < NSLOT; n += 256) {
            float v = s_scores[n];
            if (v > bv || (v == bv && n < bi)) { bv = v; bi = n; }
        }
        s_rv[tid] = bv; s_ri[tid] = bi;
        __syncthreads();
        for (int st = 128; st > 0; st >>= 1) {
            if (tid < st) {
                float ov = s_rv[tid + st]; int oi = s_ri[tid + st];
                if (ov > s_rv[tid] || (ov == s_rv[tid] && oi < s_ri[tid])) {
                    s_rv[tid] = ov; s_ri[tid] = oi;
                }
            }
            __syncthreads();
        }
        if (tid == 0) { s_idx[kk] = s_ri[0]; s_scores[s_ri[0]] = -INFINITY; }
        __syncthreads();
    }
    // attention logits over the selected 8 (full 64-d query)
    if (tid < TOPK) {
        int n = s_idx[tid];
        float a = 0.f;
        #pragma unroll
        for (int j = 0; j < BOT; j++) a += s_q[j] * aux_keys[n * BOT + j];
        s_attn[tid] = a * 0.125f + log_rel[n];   // 1/sqrt(64)
    }
    __syncthreads();
    if (tid == 0) {
        float mx = s_attn[0];
        #pragma unroll
        for (int k = 1; k < TOPK; k++) mx = fmaxf(mx, s_attn[k]);
        float sum = 0.f;
        #pragma unroll
        for (int k = 0; k < TOPK; k++) { float e = expf(s_attn[k] - mx); s_w[k] = e; sum += e; }
        float inv = 1.0f / sum;
        #pragma unroll
        for (int k = 0; k < TOPK; k++) s_w[k] *= inv;
    }
    __syncthreads();
    // t[tok] = sum_k w_k * AV[idx_k]   (VB=256 == blockDim)
    float acc = 0.f;
    #pragma unroll
    for (int k = 0; k < TOPK; k++) acc += s_w[k] * g_AV[(size_t)s_idx[k] * VB + tid];
    g_t[(size_t)tok * VB + tid] = acc;
}

// ------- final: out = h + gate(tok) * (t @ Wvu^T)  [M, HID], K=VB -----------
__global__ __launch_bounds__(256) void k_final(const float* __restrict__ hin,
                                               const float* __restrict__ Wvu,
                                               float* __restrict__ out,
                                               const float* __restrict__ bu2,
                                               const float* __restrict__ gw1p,
                                               const float* __restrict__ gbp) {
    __shared__ float As[16][68];
    __shared__ float Bs[16][68];
    int tid = threadIdx.x, tx = tid & 15, ty = tid >> 4;
    int m0 = blockIdx.y * 64, n0 = blockIdx.x * 64;
    int lr = tid >> 2, lk = (tid & 3) << 2;
    const float* ap = g_t + (size_t)(m0 + lr) * VB + lk;
    const float* bp = Wvu + (size_t)(n0 + lr) * VB + lk;
    float acc[4][4] = {};
    for (int k0 = 0; k0 < VB; k0 += 16) {
        float4 a4 = *(const float4*)(ap + k0);
        float4 b4 = *(const float4*)(bp + k0);
        As[lk + 0][lr] = a4.x; As[lk + 1][lr] = a4.y; As[lk + 2][lr] = a4.z; As[lk + 3][lr] = a4.w;
        Bs[lk + 0][lr] = b4.x; Bs[lk + 1][lr] = b4.y; Bs[lk + 2][lr] = b4.z; Bs[lk + 3][lr] = b4.w;
        __syncthreads();
        #pragma unroll
        for (int k = 0; k < 16; k++) {
            float4 av = *(const float4*)&As[k][ty << 2];
            float4 bv = *(const float4*)&Bs[k][tx << 2];
            float am[4] = {av.x, av.y, av.z, av.w};
            float bn[4] = {bv.x, bv.y, bv.z, bv.w};
            #pragma unroll
            for (int i = 0; i < 4; i++)
                #pragma unroll
                for (int j = 0; j < 4; j++) acc[i][j] += am[i] * bn[j];
        }
        __syncthreads();
    }
    float gw1 = *gw1p, gb = *gbp, b2 = *bu2, mlv = g_meanlv;
    #pragma unroll
    for (int i = 0; i < 4; i++) {
        int m = m0 + (ty << 2) + i;
        float nv = g_logvar[m] / (mlv + 1e-6f);
        float le = g_learned[m] + b2;
        float u = nv * 0.5f + sigmoidf(le) * 2.5f;
        u = fminf(fmaxf(u, 0.0f), 5.0f);
        float un = fminf(fmaxf((u - 0.5f) * (1.0f / 1.5f), 0.0f), 1.0f);
        float gate = sigmoidf(gw1 * un + gb);
        if (gate < 0.05f) gate = 0.0f;
        size_t off = (size_t)m * HID + n0 + (tx << 2);
        float4 h4 = *(const float4*)&hin[off];
        float4 o;
        o.x = h4.x + gate * acc[i][0];
        o.y = h4.y + gate * acc[i][1];
        o.z = h4.z + gate * acc[i][2];
        o.w = h4.w + gate * acc[i][3];
        *(float4*)&out[off] = o;
    }
}

// ---------------------------------------------------------------------------
extern "C" void kernel_launch(void* const* d_in, const int* in_sizes, int n_in,
                              void* d_out, int out_size) {
    const float* h         = (const float*)d_in[0];
    const float* Wq        = (const float*)d_in[1];
    const float* Wr        = (const float*)d_in[2];
    const float* aux_keys  = (const float*)d_in[3];
    const float* aux_vals  = (const float*)d_in[4];
    const float* Wvd       = (const float*)d_in[5];
    const float* Wvu       = (const float*)d_in[6];
    const float* Wu1       = (const float*)d_in[7];
    const float* bu1       = (const float*)d_in[8];
    const float* Wu2       = (const float*)d_in[9];
    const float* bu2       = (const float*)d_in[10];
    const float* gate_w1   = (const float*)d_in[11];
    const float* gate_bias = (const float*)d_in[12];
    const float* log_rel   = (const float*)d_in[13];
    float* out = (float*)d_out;

    int M = in_sizes[0] / HID;   // 4096 tokens (B=2, S=2048)
    if (M > MAXTOK) M = MAXTOK;

    k_zero<<<(M + 255) / 256, 256>>>(M);
    k_rk<<<NSLOT, 64>>>(aux_keys, Wr);
    k_av<<<dim3(VB / 64, NSLOT / 64), 256>>>(aux_vals, Wvd);
    k_qvar<<<M / 64, 256>>>(h, Wq);
    k_learned<<<dim3(NSLOT / 64, M / 64), 256>>>(h, Wu1, bu1, Wu2);
    k_mean<<<1, 256>>>(M);
    k_router<<<M, 256>>>(aux_keys, Wr, log_rel);
    k_final<<<dim3(HID / 64, M / 64), 256>>>(h, Wvu, out, bu2, gate_w1, gate_bias);
}

// round 2
// speedup vs baseline: 2.9430x; 2.9430x over previous
#include <cuda_runtime.h>
#include <cuda_bf16.h>
#include <math.h>

#define HID   4096
#define BOT   64
#define RDIM  48
#define NSLOT 1024
#define TOPK  8
#define VB    256
#define MAXTOK 4096
#define NWB   1152   // 1024 Wu1 rows + 64 Wq rows + 64 zero pad

// ---------------- scratch (device globals; no allocations allowed) ----------
__device__ float g_q[MAXTOK * BOT];
__device__ float g_rk[NSLOT * RDIM];
__device__ float g_AV[NSLOT * VB];
__device__ float g_logvar[MAXTOK];
__device__ float g_learned[MAXTOK];
__device__ float g_meanlv;
__device__ __nv_bfloat16 g_hb[(size_t)MAXTOK * HID];   // bf16 copy of h
__device__ __nv_bfloat16 g_wb[(size_t)NWB * HID];      // [Wu1 ; Wq ; 0]
__device__ __nv_bfloat16 g_avb[(size_t)NSLOT * HID];   // bf16 aux_values
__device__ __nv_bfloat16 g_wvdb[(size_t)VB * HID];     // bf16 Wvd
__device__ __nv_bfloat16 g_wvub[(size_t)HID * VB];     // bf16 Wvu
__device__ __nv_bfloat16 g_tb[(size_t)MAXTOK * VB];    // bf16 t vectors

__device__ __forceinline__ float gelu_tanh(float x) {
    float x3 = x * x * x;
    float t = tanhf(0.7978845608028654f * (x + 0.044715f * x3));
    return 0.5f * x * (1.0f + t);
}
__device__ __forceinline__ float sigmoidf(float x) {
    return 1.0f / (1.0f + expf(-x));
}

// ---------------- mma helpers ----------------
__device__ __forceinline__ void ldsm4(unsigned r[4], unsigned addr) {
    asm volatile("ldmatrix.sync.aligned.m8n8.x4.shared.b16 {%0,%1,%2,%3}, [%4];"
                 : "=r"(r[0]), "=r"(r[1]), "=r"(r[2]), "=r"(r[3]) : "r"(addr));
}
__device__ __forceinline__ void mma16816(float c[4], const unsigned a[4], const unsigned b0, const unsigned b1) {
    asm("mma.sync.aligned.m16n8k16.row.col.f32.bf16.bf16.f32 "
        "{%0,%1,%2,%3}, {%4,%5,%6,%7}, {%8,%9}, {%0,%1,%2,%3};"
        : "+f"(c[0]), "+f"(c[1]), "+f"(c[2]), "+f"(c[3])
        : "r"(a[0]), "r"(a[1]), "r"(a[2]), "r"(a[3]), "r"(b0), "r"(b1));
}

// 128x128 block tile, BK=32, 8 warps (2 M x 4 N), warp tile 64x32.
// acc[mt][nt][c]: c0=(row gID,col 2tig) c1=(gID,2tig+1) c2=(gID+8,2tig) c3=(gID+8,2tig+1)
#define SMS 40   // smem row stride in bf16 (80B: 16B-aligned, LDSM conflict-free)
__device__ __forceinline__ void gemm_tile_128x128(
    const __nv_bfloat16* __restrict__ A, const __nv_bfloat16* __restrict__ B,
    int kstride, int m0, int n0, int kbeg, int kend, float acc[4][4][4])
{
    __shared__ __align__(16) __nv_bfloat16 As[128 * SMS];
    __shared__ __align__(16) __nv_bfloat16 Bs[128 * SMS];
    const int tid = threadIdx.x;
    const int lane = tid & 31, wid = tid >> 5;
    const int warp_m = wid & 1, warp_n = wid >> 1;

    // global load mapping: 2 x uint4 per thread per tile (128 rows x 4 chunks)
    const int lr = tid >> 2, lc = (tid & 3) << 3;
    const __nv_bfloat16* Ag0 = A + (size_t)(m0 + lr) * kstride + lc;
    const __nv_bfloat16* Ag1 = Ag0 + (size_t)64 * kstride;
    const __nv_bfloat16* Bg0 = B + (size_t)(n0 + lr) * kstride + lc;
    const __nv_bfloat16* Bg1 = Bg0 + (size_t)64 * kstride;
    __nv_bfloat16* As0 = As + lr * SMS + lc;
    __nv_bfloat16* As1 = As + (lr + 64) * SMS + lc;
    __nv_bfloat16* Bs0 = Bs + lr * SMS + lc;
    __nv_bfloat16* Bs1 = Bs + (lr + 64) * SMS + lc;

    const unsigned As_u = (unsigned)__cvta_generic_to_shared(As);
    const unsigned Bs_u = (unsigned)__cvta_generic_to_shared(Bs);
    // ldmatrix lane addressing: quad = lane>>3; quad&1 -> +8 rows; quad>>1 -> +8 cols
    const int lrow8 = (lane & 7) + ((lane >> 3) & 1) * 8;
    const int lcol8 = ((lane >> 4) & 1) * 8;
    const int arow = warp_m * 64 + lrow8;
    const int brow = warp_n * 32 + lrow8;

    uint4 ra0, ra1, rb0, rb1;
    ra0 = *(const uint4*)(Ag0 + kbeg); ra1 = *(const uint4*)(Ag1 + kbeg);
    rb0 = *(const uint4*)(Bg0 + kbeg); rb1 = *(const uint4*)(Bg1 + kbeg);

    for (int kk = kbeg; kk < kend; kk += 32) {
        *(uint4*)As0 = ra0; *(uint4*)As1 = ra1;
        *(uint4*)Bs0 = rb0; *(uint4*)Bs1 = rb1;
        __syncthreads();
        if (kk + 32 < kend) {
            ra0 = *(const uint4*)(Ag0 + kk + 32); ra1 = *(const uint4*)(Ag1 + kk + 32);
            rb0 = *(const uint4*)(Bg0 + kk + 32); rb1 = *(const uint4*)(Bg1 + kk + 32);
        }
        #pragma unroll
        for (int k16 = 0; k16 < 2; ++k16) {
            unsigned af[4][4];
            #pragma unroll
            for (int mt = 0; mt < 4; ++mt)
                ldsm4(af[mt], As_u + (unsigned)(((arow + mt * 16) * SMS + lcol8 + k16 * 16) * 2));
            unsigned bfr[2][4];
            #pragma unroll
            for (int nh = 0; nh < 2; ++nh)
                ldsm4(bfr[nh], Bs_u + (unsigned)(((brow + nh * 16) * SMS + lcol8 + k16 * 16) * 2));
            #pragma unroll
            for (int mt = 0; mt < 4; ++mt)
                #pragma unroll
                for (int nt = 0; nt < 4; ++nt)
                    mma16816(acc[mt][nt], af[mt], bfr[nt >> 1][nt & 1], bfr[nt >> 1][2 + (nt & 1)]);
        }
        __syncthreads();
    }
}

// ---------------- zero scratch ----------------
__global__ void k_zero(int M) {
    int i = blockIdx.x * 256 + threadIdx.x;
    if (i < M) g_learned[i] = 0.0f;
    else if (i < M + NSLOT * VB) g_AV[i - M] = 0.0f;
}

// ---------------- convert all weights to bf16 (+ zero pad of g_wb) ----------
__device__ __forceinline__ void cvt4(__nv_bfloat16* dst, int i4, const float* src) {
    float4 v = ((const float4*)src)[i4];
    __nv_bfloat162 p0, p1;
    p0.x = __float2bfloat16(v.x); p0.y = __float2bfloat16(v.y);
    p1.x = __float2bfloat16(v.z); p1.y = __float2bfloat16(v.w);
    ((__nv_bfloat162*)dst)[i4 * 2] = p0;
    ((__nv_bfloat162*)dst)[i4 * 2 + 1] = p1;
}
__global__ void k_cvt_all(const float* __restrict__ Wu1, const float* __restrict__ Wq,
                          const float* __restrict__ av, const float* __restrict__ wvd,
                          const float* __restrict__ wvu) {
    const int N_WU1 = 1024 * HID / 4, N_WQ = 64 * HID / 4, N_Z = 64 * HID / 4;
    const int N_AV = NSLOT * HID / 4, N_WVD = VB * HID / 4, N_WVU = HID * VB / 4;
    int i = blockIdx.x * 256 + threadIdx.x;
    if (i < N_WU1) { cvt4(g_wb, i, Wu1); return; }
    i -= N_WU1;
    if (i < N_WQ) { cvt4(g_wb + (size_t)1024 * HID, i, Wq); return; }
    i -= N_WQ;
    if (i < N_Z) {
        __nv_bfloat162 z; z.x = __float2bfloat16(0.f); z.y = z.x;
        ((__nv_bfloat162*)(g_wb + (size_t)1088 * HID))[i * 2] = z;
        ((__nv_bfloat162*)(g_wb + (size_t)1088 * HID))[i * 2 + 1] = z;
        return;
    }
    i -= N_Z;
    if (i < N_AV) { cvt4(g_avb, i, av); return; }
    i -= N_AV;
    if (i < N_WVD) { cvt4(g_wvdb, i, wvd); return; }
    i -= N_WVD;
    if (i < N_WVU) { cvt4(g_wvub, i, wvu); return; }
}

// ---------------- h: fp32 -> bf16 + per-row log-variance ----------------
__global__ __launch_bounds__(256) void k_prep_h(const float* __restrict__ h) {
    __shared__ float s_s[8], s_s2[8];
    int row = blockIdx.x, tid = threadIdx.x;
    const float* src = h + (size_t)row * HID;
    __nv_bfloat16* dst = g_hb + (size_t)row * HID;
    float s = 0.f, s2 = 0.f;
    #pragma unroll
    for (int i = 0; i < 4; i++) {
        int i4 = tid + 256 * i;
        float4 v = ((const float4*)src)[i4];
        s += v.x + v.y + v.z + v.w;
        s2 += v.x * v.x + v.y * v.y + v.z * v.z + v.w * v.w;
        __nv_bfloat162 p0, p1;
        p0.x = __float2bfloat16(v.x); p0.y = __float2bfloat16(v.y);
        p1.x = __float2bfloat16(v.z); p1.y = __float2bfloat16(v.w);
        ((__nv_bfloat162*)dst)[i4 * 2] = p0;
        ((__nv_bfloat162*)dst)[i4 * 2 + 1] = p1;
    }
    #pragma unroll
    for (int o = 16; o > 0; o >>= 1) {
        s += __shfl_xor_sync(0xFFFFFFFFu, s, o);
        s2 += __shfl_xor_sync(0xFFFFFFFFu, s2, o);
    }
    if ((tid & 31) == 0) { s_s[tid >> 5] = s; s_s2[tid >> 5] = s2; }
    __syncthreads();
    if (tid == 0) {
        float ts = 0.f, ts2 = 0.f;
        #pragma unroll
        for (int w = 0; w < 8; w++) { ts += s_s[w]; ts2 += s_s2[w]; }
        float mean = ts * (1.0f / HID);
        float var = ts2 * (1.0f / HID) - mean * mean;
        g_logvar[row] = log1pf(var);
    }
}

// ---------------- rk = aux_keys @ Wr^T  [NSLOT, RDIM] (fp32, tiny) ----------
__global__ void k_rk(const float* __restrict__ aux_keys, const float* __restrict__ Wr) {
    __shared__ float kr[BOT];
    int n = blockIdx.x, tid = threadIdx.x;
    if (tid < BOT) kr[tid] = aux_keys[n * BOT + tid];
    __syncthreads();
    if (tid < RDIM) {
        float a = 0.f;
        #pragma unroll
        for (int j = 0; j < BOT; j++) a += kr[j] * Wr[tid * BOT + j];
        g_rk[n * RDIM + tid] = a;
    }
}

// ---------------- AV = aux_values @ Wvd^T (bf16 mma, split-K=8) -------------
__global__ __launch_bounds__(256) void k_mma_av() {
    int m0 = blockIdx.y * 128, n0 = blockIdx.x * 128;
    int kbeg = blockIdx.z * 512;
    float acc[4][4][4] = {};
    gemm_tile_128x128(g_avb, g_wvdb, HID, m0, n0, kbeg, kbeg + 512, acc);
    int lane = threadIdx.x & 31, wid = threadIdx.x >> 5;
    int warp_m = wid & 1, warp_n = wid >> 1;
    int gID = lane >> 2, tig = lane & 3;
    #pragma unroll
    for (int mt = 0; mt < 4; ++mt)
        #pragma unroll
        for (int rh = 0; rh < 2; ++rh) {
            int m = m0 + warp_m * 64 + mt * 16 + gID + rh * 8;
            #pragma unroll
            for (int nt = 0; nt < 4; ++nt) {
                int n = n0 + warp_n * 32 + nt * 8 + tig * 2;
                atomicAdd(&g_AV[(size_t)m * VB + n], acc[mt][nt][rh * 2]);
                atomicAdd(&g_AV[(size_t)m * VB + n + 1], acc[mt][nt][rh * 2 + 1]);
            }
        }
}

// ------- combined learned + q GEMM: g_hb @ g_wb^T, N=1152 -------------------
__global__ __launch_bounds__(256) void k_mma_learn(const float* __restrict__ bu1,
                                                   const float* __restrict__ Wu2) {
    __shared__ float s_red[128];
    int m0 = blockIdx.y * 128, n0 = blockIdx.x * 128;
    float acc[4][4][4] = {};
    gemm_tile_128x128(g_hb, g_wb, HID, m0, n0, 0, HID, acc);
    int tid = threadIdx.x, lane = tid & 31, wid = tid >> 5;
    int warp_m = wid & 1, warp_n = wid >> 1;
    int gID = lane >> 2, tig = lane & 3;

    if (n0 < 1024) {
        if (tid < 128) s_red[tid] = 0.f;
        __syncthreads();
        #pragma unroll
        for (int mt = 0; mt < 4; ++mt)
            #pragma unroll
            for (int rh = 0; rh < 2; ++rh) {
                float p = 0.f;
                #pragma unroll
                for (int nt = 0; nt < 4; ++nt) {
                    int n = n0 + warp_n * 32 + nt * 8 + tig * 2;
                    float x0 = acc[mt][nt][rh * 2] + bu1[n];
                    float x1 = acc[mt][nt][rh * 2 + 1] + bu1[n + 1];
                    p += gelu_tanh(x0) * Wu2[n] + gelu_tanh(x1) * Wu2[n + 1];
                }
                p += __shfl_xor_sync(0xFFFFFFFFu, p, 1);
                p += __shfl_xor_sync(0xFFFFFFFFu, p, 2);
                if (tig == 0)
                    atomicAdd(&s_red[warp_m * 64 + mt * 16 + gID + rh * 8], p);
            }
        __syncthreads();
        if (tid < 128) atomicAdd(&g_learned[m0 + tid], s_red[tid]);
    } else {
        // q region: n in [1024, 1088)
        #pragma unroll
        for (int mt = 0; mt < 4; ++mt)
            #pragma unroll
            for (int rh = 0; rh < 2; ++rh) {
                int m = m0 + warp_m * 64 + mt * 16 + gID + rh * 8;
                #pragma unroll
                for (int nt = 0; nt < 4; ++nt) {
                    int nq = n0 + warp_n * 32 + nt * 8 + tig * 2 - 1024;
                    if (nq < 64) {
                        g_q[(size_t)m * BOT + nq] = acc[mt][nt][rh * 2];
                        g_q[(size_t)m * BOT + nq + 1] = acc[mt][nt][rh * 2 + 1];
                    }
                }
            }
    }
}

// ---------------- mean(log_var) ----------------
__global__ void k_mean(int M) {
    __shared__ float s[256];
    int tid = threadIdx.x;
    float a = 0.f;
    for (int i = tid; i < M; i += 256) a += g_logvar[i];
    s[tid] = a; __syncthreads();
    for (int st = 128; st > 0; st >>= 1) {
        if (tid < st) s[tid] += s[tid + st];
        __syncthreads();
    }
    if (tid == 0) g_meanlv = s[0] / (float)M;
}

// ------- router: scores, top-8, softmax attn, t = sum w*AV[idx] -------------
__global__ __launch_bounds__(256) void k_router(const float* __restrict__ aux_keys,
                                                const float* __restrict__ Wr,
                                                const float* __restrict__ log_rel) {
    __shared__ float s_q[BOT];
    __shared__ float s_rq[RDIM];
    __shared__ float s_scores[NSLOT];
    __shared__ float s_rv[256];
    __shared__ int   s_ri[256];
    __shared__ int   s_idx[TOPK];
    __shared__ float s_w[TOPK];
    __shared__ float s_attn[TOPK];

    int tok = blockIdx.x, tid = threadIdx.x;
    if (tid < BOT) s_q[tid] = g_q[(size_t)tok * BOT + tid];
    __syncthreads();
    if (tid < RDIM) {
        float a = 0.f;
        #pragma unroll
        for (int j = 0; j < BOT; j++) a += s_q[j] * Wr[tid * BOT + j];
        s_rq[tid] = a;
    }
    __syncthreads();
    const float inv_sqrt_rdim = 0.14433756729740643f;
    for (int n = tid; n < NSLOT; n += 256) {
        float a = 0.f;
        #pragma unroll
        for (int r = 0; r < RDIM; r++) a += s_rq[r] * g_rk[n * RDIM + r];
        s_scores[n] = a * inv_sqrt_rdim + log_rel[n];
    }
    __syncthreads();
    for (int kk = 0; kk < TOPK; kk++) {
        float bv = -INFINITY; int bi = 0x7FFFFFFF;
        for (int n = tid; n < NSLOT; n += 256) {
            float v = s_scores[n];
            if (v > bv || (v == bv && n < bi)) { bv = v; bi = n; }
        }
        s_rv[tid] = bv; s_ri[tid] = bi;
        __syncthreads();
        for (int st = 128; st > 0; st >>= 1) {
            if (tid < st) {
                float ov = s_rv[tid + st]; int oi = s_ri[tid + st];
                if (ov > s_rv[tid] || (ov == s_rv[tid] && oi < s_ri[tid])) {
                    s_rv[tid] = ov; s_ri[tid] = oi;
                }
            }
            __syncthreads();
        }
        if (tid == 0) { s_idx[kk] = s_ri[0]; s_scores[s_ri[0]] = -INFINITY; }
        __syncthreads();
    }
    if (tid < TOPK) {
        int n = s_idx[tid];
        float a = 0.f;
        #pragma unroll
        for (int j = 0; j < BOT; j++) a += s_q[j] * aux_keys[n * BOT + j];
        s_attn[tid] = a * 0.125f + log_rel[n];
    }
    __syncthreads();
    if (tid == 0) {
        float mx = s_attn[0];
        #pragma unroll
        for (int k = 1; k < TOPK; k++) mx = fmaxf(mx, s_attn[k]);
        float sum = 0.f;
        #pragma unroll
        for (int k = 0; k < TOPK; k++) { float e = expf(s_attn[k] - mx); s_w[k] = e; sum += e; }
        float inv = 1.0f / sum;
        #pragma unroll
        for (int k = 0; k < TOPK; k++) s_w[k] *= inv;
    }
    __syncthreads();
    float acc = 0.f;
    #pragma unroll
    for (int k = 0; k < TOPK; k++) acc += s_w[k] * g_AV[(size_t)s_idx[k] * VB + tid];
    g_tb[(size_t)tok * VB + tid] = __float2bfloat16(acc);
}

// ------- final: out = h + gate * (t @ Wvu^T)  (bf16 mma, K=256) -------------
__global__ __launch_bounds__(256) void k_mma_fin(const float* __restrict__ hin,
                                                 float* __restrict__ out,
                                                 const float* __restrict__ bu2,
                                                 const float* __restrict__ gw1p,
                                                 const float* __restrict__ gbp) {
    int m0 = blockIdx.y * 128, n0 = blockIdx.x * 128;
    float acc[4][4][4] = {};
    gemm_tile_128x128(g_tb, g_wvub, VB, m0, n0, 0, VB, acc);
    int lane = threadIdx.x & 31, wid = threadIdx.x >> 5;
    int warp_m = wid & 1, warp_n = wid >> 1;
    int gID = lane >> 2, tig = lane & 3;
    float gw1 = *gw1p, gb = *gbp, b2 = *bu2, mlv = g_meanlv;
    #pragma unroll
    for (int mt = 0; mt < 4; ++mt)
        #pragma unroll
        for (int rh = 0; rh < 2; ++rh) {
            int m = m0 + warp_m * 64 + mt * 16 + gID + rh * 8;
            float nv = g_logvar[m] / (mlv + 1e-6f);
            float le = g_learned[m] + b2;
            float u = nv * 0.5f + sigmoidf(le) * 2.5f;
            u = fminf(fmaxf(u, 0.0f), 5.0f);
            float un = fminf(fmaxf((u - 0.5f) * (1.0f / 1.5f), 0.0f), 1.0f);
            float gate = sigmoidf(gw1 * un + gb);
            if (gate < 0.05f) gate = 0.0f;
            #pragma unroll
            for (int nt = 0; nt < 4; ++nt) {
                int n = n0 + warp_n * 32 + nt * 8 + tig * 2;
                size_t off = (size_t)m * HID + n;
                float2 h2 = *(const float2*)&hin[off];
                float2 o;
                o.x = h2.x + gate * acc[mt][nt][rh * 2];
                o.y = h2.y + gate * acc[mt][nt][rh * 2 + 1];
                *(float2*)&out[off] = o;
            }
        }
}

// ---------------------------------------------------------------------------
extern "C" void kernel_launch(void* const* d_in, const int* in_sizes, int n_in,
                              void* d_out, int out_size) {
    const float* h         = (const float*)d_in[0];
    const float* Wq        = (const float*)d_in[1];
    const float* Wr        = (const float*)d_in[2];
    const float* aux_keys  = (const float*)d_in[3];
    const float* aux_vals  = (const float*)d_in[4];
    const float* Wvd       = (const float*)d_in[5];
    const float* Wvu       = (const float*)d_in[6];
    const float* Wu1       = (const float*)d_in[7];
    const float* bu1       = (const float*)d_in[8];
    const float* Wu2       = (const float*)d_in[9];
    const float* bu2       = (const float*)d_in[10];
    const float* gate_w1   = (const float*)d_in[11];
    const float* gate_bias = (const float*)d_in[12];
    const float* log_rel   = (const float*)d_in[13];
    float* out = (float*)d_out;

    int M = in_sizes[0] / HID;   // 4096 tokens
    if (M > MAXTOK) M = MAXTOK;

    const int CVT_BLOCKS = (1024 * HID / 4 + 64 * HID / 4 + 64 * HID / 4 +
                            NSLOT * HID / 4 + VB * HID / 4 + HID * VB / 4 + 255) / 256;

    k_zero<<<(M + NSLOT * VB + 255) / 256, 256>>>(M);
    k_cvt_all<<<CVT_BLOCKS, 256>>>(Wu1, Wq, aux_vals, Wvd, Wvu);
    k_prep_h<<<M, 256>>>(h);
    k_rk<<<NSLOT, 64>>>(aux_keys, Wr);
    k_mma_av<<<dim3(VB / 128, NSLOT / 128, 8), 256>>>();
    k_mma_learn<<<dim3(NWB / 128, M / 128), 256>>>(bu1, Wu2);
    k_mean<<<1, 256>>>(M);
    k_router<<<M, 256>>>(aux_keys, Wr, log_rel);
    k_mma_fin<<<dim3(HID / 128, M / 128), 256>>>(h, out, bu2, gate_w1, gate_bias);
}

// round 3
// speedup vs baseline: 5.2247x; 1.7753x over previous
#include <cuda_runtime.h>
#include <cuda_bf16.h>
#include <math.h>

#define HID   4096
#define BOT   64
#define RDIM  48
#define NSLOT 1024
#define TOPK  8
#define VB    256
#define MAXTOK 4096
#define NWB   1152   // 1024 Wu1 rows + 64 Wq rows + 64 zero pad

#define SMS    40           // smem row stride in bf16 (80B)
#define STAGES 4
#define STAGE_BYTES (128 * SMS * 2)
#define SMEM_BYTES  (2 * STAGES * STAGE_BYTES)   // 81920

// ---------------- scratch (device globals; no allocations allowed) ----------
__device__ float g_q[MAXTOK * BOT];
__device__ float g_rk[NSLOT * RDIM];
__device__ float g_AV[NSLOT * VB];
__device__ float g_scores[(size_t)MAXTOK * NSLOT];
__device__ float g_logvar[MAXTOK];
__device__ float g_learned[MAXTOK];
__device__ float g_meanlv;
__device__ __nv_bfloat16 g_hb[(size_t)MAXTOK * HID];
__device__ __nv_bfloat16 g_wb[(size_t)NWB * HID];
__device__ __nv_bfloat16 g_avb[(size_t)NSLOT * HID];
__device__ __nv_bfloat16 g_wvdb[(size_t)VB * HID];
__device__ __nv_bfloat16 g_wvub[(size_t)HID * VB];
__device__ __nv_bfloat16 g_tb[(size_t)MAXTOK * VB];

extern __shared__ __align__(16) unsigned char dynsmem[];

__device__ __forceinline__ float gelu_tanh(float x) {
    float x3 = x * x * x;
    float t = tanhf(0.7978845608028654f * (x + 0.044715f * x3));
    return 0.5f * x * (1.0f + t);
}
__device__ __forceinline__ float sigmoidf(float x) {
    return 1.0f / (1.0f + expf(-x));
}

// ---------------- mma / cp.async helpers ----------------
__device__ __forceinline__ void ldsm4(unsigned r[4], unsigned addr) {
    asm volatile("ldmatrix.sync.aligned.m8n8.x4.shared.b16 {%0,%1,%2,%3}, [%4];"
                 : "=r"(r[0]), "=r"(r[1]), "=r"(r[2]), "=r"(r[3]) : "r"(addr));
}
__device__ __forceinline__ void mma16816(float c[4], const unsigned a[4], const unsigned b0, const unsigned b1) {
    asm("mma.sync.aligned.m16n8k16.row.col.f32.bf16.bf16.f32 "
        "{%0,%1,%2,%3}, {%4,%5,%6,%7}, {%8,%9}, {%0,%1,%2,%3};"
        : "+f"(c[0]), "+f"(c[1]), "+f"(c[2]), "+f"(c[3])
        : "r"(a[0]), "r"(a[1]), "r"(a[2]), "r"(a[3]), "r"(b0), "r"(b1));
}
__device__ __forceinline__ void cpasync16(unsigned saddr, const void* g) {
    asm volatile("cp.async.cg.shared.global [%0], [%1], 16;" :: "r"(saddr), "l"(g));
}
__device__ __forceinline__ void cpcommit() { asm volatile("cp.async.commit_group;"); }
__device__ __forceinline__ void cpwait2() { asm volatile("cp.async.wait_group 2;"); }

// 128x128 block tile, BK=32, 4-stage cp.async pipeline, 8 warps (2M x 4N).
__device__ __forceinline__ void gemm_tile_128x128(
    const __nv_bfloat16* __restrict__ A, const __nv_bfloat16* __restrict__ B,
    int kstride, int m0, int n0, int kbeg, int kend, float acc[4][4][4])
{
    __nv_bfloat16* As = (__nv_bfloat16*)dynsmem;
    __nv_bfloat16* Bs = As + STAGES * 128 * SMS;
    const int tid = threadIdx.x;
    const int lane = tid & 31, wid = tid >> 5;
    const int warp_m = wid & 1, warp_n = wid >> 1;

    const int lr = tid >> 2, lc = (tid & 3) << 3;
    const __nv_bfloat16* Ag0 = A + (size_t)(m0 + lr) * kstride + lc;
    const __nv_bfloat16* Ag1 = Ag0 + (size_t)64 * kstride;
    const __nv_bfloat16* Bg0 = B + (size_t)(n0 + lr) * kstride + lc;
    const __nv_bfloat16* Bg1 = Bg0 + (size_t)64 * kstride;

    const unsigned As_u = (unsigned)__cvta_generic_to_shared(As);
    const unsigned Bs_u = (unsigned)__cvta_generic_to_shared(Bs);
    const unsigned sa0 = As_u + (unsigned)((lr * SMS + lc) * 2);
    const unsigned sa1 = As_u + (unsigned)(((lr + 64) * SMS + lc) * 2);
    const unsigned sb0 = Bs_u + (unsigned)((lr * SMS + lc) * 2);
    const unsigned sb1 = Bs_u + (unsigned)(((lr + 64) * SMS + lc) * 2);

    const int lrow8 = (lane & 7) + ((lane >> 3) & 1) * 8;
    const int lcol8 = ((lane >> 4) & 1) * 8;
    const int arow = warp_m * 64 + lrow8;
    const int brow = warp_n * 32 + lrow8;

    const int NIT = (kend - kbeg) >> 5;

    #pragma unroll
    for (int s = 0; s < STAGES - 1; ++s) {
        unsigned so = s * STAGE_BYTES;
        int ko = kbeg + s * 32;
        cpasync16(sa0 + so, Ag0 + ko); cpasync16(sa1 + so, Ag1 + ko);
        cpasync16(sb0 + so, Bg0 + ko); cpasync16(sb1 + so, Bg1 + ko);
        cpcommit();
    }

    for (int kt = 0; kt < NIT; ++kt) {
        cpwait2();
        __syncthreads();
        int nxt = kt + STAGES - 1;
        if (nxt < NIT) {
            unsigned so = (nxt & (STAGES - 1)) * STAGE_BYTES;
            int ko = kbeg + nxt * 32;
            cpasync16(sa0 + so, Ag0 + ko); cpasync16(sa1 + so, Ag1 + ko);
            cpasync16(sb0 + so, Bg0 + ko); cpasync16(sb1 + so, Bg1 + ko);
        }
        cpcommit();
        unsigned cso = (kt & (STAGES - 1)) * STAGE_BYTES;
        #pragma unroll
        for (int k16 = 0; k16 < 2; ++k16) {
            unsigned af[4][4];
            #pragma unroll
            for (int mt = 0; mt < 4; ++mt)
                ldsm4(af[mt], As_u + cso + (unsigned)(((arow + mt * 16) * SMS + lcol8 + k16 * 16) * 2));
            unsigned bfr[2][4];
            #pragma unroll
            for (int nh = 0; nh < 2; ++nh)
                ldsm4(bfr[nh], Bs_u + cso + (unsigned)(((brow + nh * 16) * SMS + lcol8 + k16 * 16) * 2));
            #pragma unroll
            for (int mt = 0; mt < 4; ++mt)
                #pragma unroll
                for (int nt = 0; nt < 4; ++nt)
                    mma16816(acc[mt][nt], af[mt], bfr[nt >> 1][nt & 1], bfr[nt >> 1][2 + (nt & 1)]);
        }
    }
    __syncthreads();
}

// ---------------- zero scratch ----------------
__global__ void k_zero(int M) {
    int i = blockIdx.x * 256 + threadIdx.x;
    if (i < M) g_learned[i] = 0.0f;
    else if (i < M + NSLOT * VB) g_AV[i - M] = 0.0f;
}

// ---------------- convert weights to bf16 ----------------
__device__ __forceinline__ void cvt4(__nv_bfloat16* dst, int i4, const float* src) {
    float4 v = ((const float4*)src)[i4];
    __nv_bfloat162 p0, p1;
    p0.x = __float2bfloat16(v.x); p0.y = __float2bfloat16(v.y);
    p1.x = __float2bfloat16(v.z); p1.y = __float2bfloat16(v.w);
    ((__nv_bfloat162*)dst)[i4 * 2] = p0;
    ((__nv_bfloat162*)dst)[i4 * 2 + 1] = p1;
}
__global__ void k_cvt_all(const float* __restrict__ Wu1, const float* __restrict__ Wq,
                          const float* __restrict__ av, const float* __restrict__ wvd,
                          const float* __restrict__ wvu) {
    const int N_WU1 = 1024 * HID / 4, N_WQ = 64 * HID / 4, N_Z = 64 * HID / 4;
    const int N_AV = NSLOT * HID / 4, N_WVD = VB * HID / 4, N_WVU = HID * VB / 4;
    int i = blockIdx.x * 256 + threadIdx.x;
    if (i < N_WU1) { cvt4(g_wb, i, Wu1); return; }
    i -= N_WU1;
    if (i < N_WQ) { cvt4(g_wb + (size_t)1024 * HID, i, Wq); return; }
    i -= N_WQ;
    if (i < N_Z) {
        __nv_bfloat162 z; z.x = __float2bfloat16(0.f); z.y = z.x;
        ((__nv_bfloat162*)(g_wb + (size_t)1088 * HID))[i * 2] = z;
        ((__nv_bfloat162*)(g_wb + (size_t)1088 * HID))[i * 2 + 1] = z;
        return;
    }
    i -= N_Z;
    if (i < N_AV) { cvt4(g_avb, i, av); return; }
    i -= N_AV;
    if (i < N_WVD) { cvt4(g_wvdb, i, wvd); return; }
    i -= N_WVD;
    if (i < N_WVU) { cvt4(g_wvub, i, wvu); return; }
}

// ---------------- h: fp32 -> bf16 + per-row log-variance ----------------
__global__ __launch_bounds__(256) void k_prep_h(const float* __restrict__ h) {
    __shared__ float s_s[8], s_s2[8];
    int row = blockIdx.x, tid = threadIdx.x;
    const float* src = h + (size_t)row * HID;
    __nv_bfloat16* dst = g_hb + (size_t)row * HID;
    float s = 0.f, s2 = 0.f;
    #pragma unroll
    for (int i = 0; i < 4; i++) {
        int i4 = tid + 256 * i;
        float4 v = ((const float4*)src)[i4];
        s += v.x + v.y + v.z + v.w;
        s2 += v.x * v.x + v.y * v.y + v.z * v.z + v.w * v.w;
        __nv_bfloat162 p0, p1;
        p0.x = __float2bfloat16(v.x); p0.y = __float2bfloat16(v.y);
        p1.x = __float2bfloat16(v.z); p1.y = __float2bfloat16(v.w);
        ((__nv_bfloat162*)dst)[i4 * 2] = p0;
        ((__nv_bfloat162*)dst)[i4 * 2 + 1] = p1;
    }
    #pragma unroll
    for (int o = 16; o > 0; o >>= 1) {
        s += __shfl_xor_sync(0xFFFFFFFFu, s, o);
        s2 += __shfl_xor_sync(0xFFFFFFFFu, s2, o);
    }
    if ((tid & 31) == 0) { s_s[tid >> 5] = s; s_s2[tid >> 5] = s2; }
    __syncthreads();
    if (tid == 0) {
        float ts = 0.f, ts2 = 0.f;
        #pragma unroll
        for (int w = 0; w < 8; w++) { ts += s_s[w]; ts2 += s_s2[w]; }
        float mean = ts * (1.0f / HID);
        float var = ts2 * (1.0f / HID) - mean * mean;
        g_logvar[row] = log1pf(var);
    }
}

// ---------------- rk = aux_keys @ Wr^T  [NSLOT, RDIM] ----------------
__global__ __launch_bounds__(256) void k_rk(const float* __restrict__ aux_keys,
                                            const float* __restrict__ Wr) {
    __shared__ float sw[RDIM * BOT];     // 12KB
    __shared__ float sk[16 * BOT];       // 4KB
    int tid = threadIdx.x, s0 = blockIdx.x * 16;
    #pragma unroll
    for (int i = 0; i < 12; i++) sw[tid + 256 * i] = Wr[tid + 256 * i];
    #pragma unroll
    for (int i = 0; i < 4; i++) sk[tid + 256 * i] = aux_keys[s0 * BOT + tid + 256 * i];
    __syncthreads();
    #pragma unroll
    for (int i = 0; i < 3; i++) {
        int idx = tid + 256 * i;          // 768 outputs
        int s = idx / RDIM, r = idx - s * RDIM;
        float a = 0.f;
        #pragma unroll
        for (int j = 0; j < BOT; j++) a += sk[s * BOT + j] * sw[r * BOT + j];
        g_rk[(s0 + s) * RDIM + r] = a;
    }
}

// ---------------- AV = aux_values @ Wvd^T (bf16 mma, split-K=8) -------------
__global__ __launch_bounds__(256) void k_mma_av() {
    int m0 = blockIdx.y * 128, n0 = blockIdx.x * 128;
    int kbeg = blockIdx.z * 512;
    float acc[4][4][4] = {};
    gemm_tile_128x128(g_avb, g_wvdb, HID, m0, n0, kbeg, kbeg + 512, acc);
    int lane = threadIdx.x & 31, wid = threadIdx.x >> 5;
    int warp_m = wid & 1, warp_n = wid >> 1;
    int gID = lane >> 2, tig = lane & 3;
    #pragma unroll
    for (int mt = 0; mt < 4; ++mt)
        #pragma unroll
        for (int rh = 0; rh < 2; ++rh) {
            int m = m0 + warp_m * 64 + mt * 16 + gID + rh * 8;
            #pragma unroll
            for (int nt = 0; nt < 4; ++nt) {
                int n = n0 + warp_n * 32 + nt * 8 + tig * 2;
                atomicAdd(&g_AV[(size_t)m * VB + n], acc[mt][nt][rh * 2]);
                atomicAdd(&g_AV[(size_t)m * VB + n + 1], acc[mt][nt][rh * 2 + 1]);
            }
        }
}

// ------- combined learned + q GEMM: g_hb @ g_wb^T, N=1152 -------------------
__global__ __launch_bounds__(256) void k_mma_learn(const float* __restrict__ bu1,
                                                   const float* __restrict__ Wu2) {
    __shared__ float s_red[128];
    int m0 = blockIdx.y * 128, n0 = blockIdx.x * 128;
    float acc[4][4][4] = {};
    gemm_tile_128x128(g_hb, g_wb, HID, m0, n0, 0, HID, acc);
    int tid = threadIdx.x, lane = tid & 31, wid = tid >> 5;
    int warp_m = wid & 1, warp_n = wid >> 1;
    int gID = lane >> 2, tig = lane & 3;

    if (n0 < 1024) {
        if (tid < 128) s_red[tid] = 0.f;
        __syncthreads();
        #pragma unroll
        for (int mt = 0; mt < 4; ++mt)
            #pragma unroll
            for (int rh = 0; rh < 2; ++rh) {
                float p = 0.f;
                #pragma unroll
                for (int nt = 0; nt < 4; ++nt) {
                    int n = n0 + warp_n * 32 + nt * 8 + tig * 2;
                    float x0 = acc[mt][nt][rh * 2] + bu1[n];
                    float x1 = acc[mt][nt][rh * 2 + 1] + bu1[n + 1];
                    p += gelu_tanh(x0) * Wu2[n] + gelu_tanh(x1) * Wu2[n + 1];
                }
                p += __shfl_xor_sync(0xFFFFFFFFu, p, 1);
                p += __shfl_xor_sync(0xFFFFFFFFu, p, 2);
                if (tig == 0)
                    atomicAdd(&s_red[warp_m * 64 + mt * 16 + gID + rh * 8], p);
            }
        __syncthreads();
        if (tid < 128) atomicAdd(&g_learned[m0 + tid], s_red[tid]);
    } else {
        #pragma unroll
        for (int mt = 0; mt < 4; ++mt)
            #pragma unroll
            for (int rh = 0; rh < 2; ++rh) {
                int m = m0 + warp_m * 64 + mt * 16 + gID + rh * 8;
                #pragma unroll
                for (int nt = 0; nt < 4; ++nt) {
                    int nq = n0 + warp_n * 32 + nt * 8 + tig * 2 - 1024;
                    if (nq < 64) {
                        g_q[(size_t)m * BOT + nq] = acc[mt][nt][rh * 2];
                        g_q[(size_t)m * BOT + nq + 1] = acc[mt][nt][rh * 2 + 1];
                    }
                }
            }
    }
}

// ---------------- mean(log_var) ----------------
__global__ void k_mean(int M) {
    __shared__ float s[256];
    int tid = threadIdx.x;
    float a = 0.f;
    for (int i = tid; i < M; i += 256) a += g_logvar[i];
    s[tid] = a; __syncthreads();
    for (int st = 128; st > 0; st >>= 1) {
        if (tid < st) s[tid] += s[tid + st];
        __syncthreads();
    }
    if (tid == 0) g_meanlv = s[0] / (float)M;
}

// ------- scores[t,n] = (q_t @ Wr^T) . rk_n / sqrt(48) + log_rel[n] ----------
// 64 tokens per block; Wr, rk tiles staged through smem.
__global__ __launch_bounds__(256) void k_scores(const float* __restrict__ Wr,
                                                const float* __restrict__ log_rel) {
    __shared__ float sq[64 * 65];
    __shared__ float srq[64 * 49];
    __shared__ float srk[RDIM * BOT];    // Wr first, then rk tiles (64*48)
    int tid = threadIdx.x, t0 = blockIdx.x * 64;
    #pragma unroll
    for (int i = 0; i < 16; i++) {
        int idx = tid + 256 * i;
        int t = idx >> 6, c = idx & 63;
        sq[t * 65 + c] = g_q[(size_t)(t0 + t) * BOT + c];
    }
    #pragma unroll
    for (int i = 0; i < 12; i++) srk[tid + 256 * i] = Wr[tid + 256 * i];
    __syncthreads();
    #pragma unroll
    for (int i = 0; i < 12; i++) {
        int idx = tid + 256 * i;          // 3072 = 64*48
        int t = idx / RDIM, r = idx - t * RDIM;
        float a = 0.f;
        #pragma unroll
        for (int j = 0; j < BOT; j++) a += sq[t * 65 + j] * srk[r * BOT + j];
        srq[t * 49 + r] = a;
    }
    __syncthreads();
    const float inv_sqrt_rdim = 0.14433756729740643f;
    for (int nt = 0; nt < 16; nt++) {
        __syncthreads();
        #pragma unroll
        for (int i = 0; i < 12; i++) {
            int idx = tid + 256 * i;      // 3072 = 64 slots * 48
            srk[idx] = g_rk[(size_t)(nt * 64) * RDIM + idx];
        }
        __syncthreads();
        #pragma unroll
        for (int i = 0; i < 16; i++) {
            int idx = tid + 256 * i;      // 4096 = 64 tokens * 64 slots
            int t = idx >> 6, s = idx & 63;
            float a = 0.f;
            #pragma unroll
            for (int r = 0; r < RDIM; r++) a += srq[t * 49 + r] * srk[s * RDIM + r];
            int n = nt * 64 + s;
            g_scores[(size_t)(t0 + t) * NSLOT + n] = a * inv_sqrt_rdim + log_rel[n];
        }
    }
}

// ------- topk: per-token top-8, attn softmax, t = sum w*AV[idx] -------------
__global__ __launch_bounds__(256) void k_topk(const float* __restrict__ aux_keys,
                                              const float* __restrict__ log_rel) {
    __shared__ float s_q[BOT];
    __shared__ float s_scores[NSLOT];
    __shared__ float s_rv[256];
    __shared__ int   s_ri[256];
    __shared__ int   s_idx[TOPK];
    __shared__ float s_w[TOPK];
    __shared__ float s_attn[TOPK];

    int tok = blockIdx.x, tid = threadIdx.x;
    if (tid < BOT) s_q[tid] = g_q[(size_t)tok * BOT + tid];
    #pragma unroll
    for (int i = 0; i < 4; i++)
        s_scores[tid + 256 * i] = g_scores[(size_t)tok * NSLOT + tid + 256 * i];
    __syncthreads();
    for (int kk = 0; kk < TOPK; kk++) {
        float bv = -INFINITY; int bi = 0x7FFFFFFF;
        #pragma unroll
        for (int i = 0; i < 4; i++) {
            int n = tid + 256 * i;
            float v = s_scores[n];
            if (v > bv || (v == bv && n < bi)) { bv = v; bi = n; }
        }
        s_rv[tid] = bv; s_ri[tid] = bi;
        __syncthreads();
        for (int st = 128; st > 0; st >>= 1) {
            if (tid < st) {
                float ov = s_rv[tid + st]; int oi = s_ri[tid + st];
                if (ov > s_rv[tid] || (ov == s_rv[tid] && oi < s_ri[tid])) {
                    s_rv[tid] = ov; s_ri[tid] = oi;
                }
            }
            __syncthreads();
        }
        if (tid == 0) { s_idx[kk] = s_ri[0]; s_scores[s_ri[0]] = -INFINITY; }
        __syncthreads();
    }
    if (tid < TOPK) {
        int n = s_idx[tid];
        float a = 0.f;
        #pragma unroll
        for (int j = 0; j < BOT; j++) a += s_q[j] * aux_keys[n * BOT + j];
        s_attn[tid] = a * 0.125f + log_rel[n];
    }
    __syncthreads();
    if (tid == 0) {
        float mx = s_attn[0];
        #pragma unroll
        for (int k = 1; k < TOPK; k++) mx = fmaxf(mx, s_attn[k]);
        float sum = 0.f;
        #pragma unroll
        for (int k = 0; k < TOPK; k++) { float e = expf(s_attn[k] - mx); s_w[k] = e; sum += e; }
        float inv = 1.0f / sum;
        #pragma unroll
        for (int k = 0; k < TOPK; k++) s_w[k] *= inv;
    }
    __syncthreads();
    float acc = 0.f;
    #pragma unroll
    for (int k = 0; k < TOPK; k++) acc += s_w[k] * g_AV[(size_t)s_idx[k] * VB + tid];
    g_tb[(size_t)tok * VB + tid] = __float2bfloat16(acc);
}

// ------- final: out = h + gate * (t @ Wvu^T)  (bf16 mma, K=256) -------------
__global__ __launch_bounds__(256) void k_mma_fin(const float* __restrict__ hin,
                                                 float* __restrict__ out,
                                                 const float* __restrict__ bu2,
                                                 const float* __restrict__ gw1p,
                                                 const float* __restrict__ gbp) {
    int m0 = blockIdx.y * 128, n0 = blockIdx.x * 128;
    float acc[4][4][4] = {};
    gemm_tile_128x128(g_tb, g_wvub, VB, m0, n0, 0, VB, acc);
    int lane = threadIdx.x & 31, wid = threadIdx.x >> 5;
    int warp_m = wid & 1, warp_n = wid >> 1;
    int gID = lane >> 2, tig = lane & 3;
    float gw1 = *gw1p, gb = *gbp, b2 = *bu2, mlv = g_meanlv;
    #pragma unroll
    for (int mt = 0; mt < 4; ++mt)
        #pragma unroll
        for (int rh = 0; rh < 2; ++rh) {
            int m = m0 + warp_m * 64 + mt * 16 + gID + rh * 8;
            float nv = g_logvar[m] / (mlv + 1e-6f);
            float le = g_learned[m] + b2;
            float u = nv * 0.5f + sigmoidf(le) * 2.5f;
            u = fminf(fmaxf(u, 0.0f), 5.0f);
            float un = fminf(fmaxf((u - 0.5f) * (1.0f / 1.5f), 0.0f), 1.0f);
            float gate = sigmoidf(gw1 * un + gb);
            if (gate < 0.05f) gate = 0.0f;
            #pragma unroll
            for (int nt = 0; nt < 4; ++nt) {
                int n = n0 + warp_n * 32 + nt * 8 + tig * 2;
                size_t off = (size_t)m * HID + n;
                float2 h2 = *(const float2*)&hin[off];
                float2 o;
                o.x = h2.x + gate * acc[mt][nt][rh * 2];
                o.y = h2.y + gate * acc[mt][nt][rh * 2 + 1];
                *(float2*)&out[off] = o;
            }
        }
}

// ---------------------------------------------------------------------------
extern "C" void kernel_launch(void* const* d_in, const int* in_sizes, int n_in,
                              void* d_out, int out_size) {
    const float* h         = (const float*)d_in[0];
    const float* Wq        = (const float*)d_in[1];
    const float* Wr        = (const float*)d_in[2];
    const float* aux_keys  = (const float*)d_in[3];
    const float* aux_vals  = (const float*)d_in[4];
    const float* Wvd       = (const float*)d_in[5];
    const float* Wvu       = (const float*)d_in[6];
    const float* Wu1       = (const float*)d_in[7];
    const float* bu1       = (const float*)d_in[8];
    const float* Wu2       = (const float*)d_in[9];
    const float* bu2       = (const float*)d_in[10];
    const float* gate_w1   = (const float*)d_in[11];
    const float* gate_bias = (const float*)d_in[12];
    const float* log_rel   = (const float*)d_in[13];
    float* out = (float*)d_out;

    int M = in_sizes[0] / HID;
    if (M > MAXTOK) M = MAXTOK;

    static bool attr_done = false;
    if (!attr_done) {
        cudaFuncSetAttribute(k_mma_av,    cudaFuncAttributeMaxDynamicSharedMemorySize, SMEM_BYTES);
        cudaFuncSetAttribute(k_mma_learn, cudaFuncAttributeMaxDynamicSharedMemorySize, SMEM_BYTES);
        cudaFuncSetAttribute(k_mma_fin,   cudaFuncAttributeMaxDynamicSharedMemorySize, SMEM_BYTES);
        attr_done = true;
    }

    const int CVT_BLOCKS = (1024 * HID / 4 + 64 * HID / 4 + 64 * HID / 4 +
                            NSLOT * HID / 4 + VB * HID / 4 + HID * VB / 4 + 255) / 256;

    k_zero<<<(M + NSLOT * VB + 255) / 256, 256>>>(M);
    k_cvt_all<<<CVT_BLOCKS, 256>>>(Wu1, Wq, aux_vals, Wvd, Wvu);
    k_prep_h<<<M, 256>>>(h);
    k_rk<<<NSLOT / 16, 256>>>(aux_keys, Wr);
    k_mma_av<<<dim3(VB / 128, NSLOT / 128, 8), 256, SMEM_BYTES>>>();
    k_mma_learn<<<dim3(NWB / 128, M / 128), 256, SMEM_BYTES>>>(bu1, Wu2);
    k_mean<<<1, 256>>>(M);
    k_scores<<<M / 64, 256>>>(Wr, log_rel);
    k_topk<<<M, 256>>>(aux_keys, log_rel);
    k_mma_fin<<<dim3(HID / 128, M / 128), 256, SMEM_BYTES>>>(h, out, bu2, gate_w1, gate_bias);
}

// round 4
// speedup vs baseline: 5.3643x; 1.0267x over previous
#include <cuda_runtime.h>
#include <cuda_bf16.h>
#include <math.h>

#define HID   4096
#define BOT   64
#define RDIM  48
#define NSLOT 1024
#define TOPK  8
#define VB    256
#define MAXTOK 4096
#define NWB   1152   // 1024 Wu1 rows + 64 Wq rows + 64 zero pad

#define SMS    40           // smem row stride in bf16 (80B)
#define STAGES 4
#define STAGE_BYTES (128 * SMS * 2)
#define SMEM_BYTES  (2 * STAGES * STAGE_BYTES)   // 81920

// ---------------- scratch (device globals; no allocations allowed) ----------
__device__ float g_q[MAXTOK * BOT];
__device__ float g_rk[NSLOT * RDIM];
__device__ float g_AV[NSLOT * VB];
__device__ float g_scores[(size_t)MAXTOK * NSLOT];
__device__ float g_logvar[MAXTOK];
__device__ float g_learned[MAXTOK];
__device__ float g_meanlv;
__device__ __nv_bfloat16 g_hb[(size_t)MAXTOK * HID];
__device__ __nv_bfloat16 g_wb[(size_t)NWB * HID];
__device__ __nv_bfloat16 g_avb[(size_t)NSLOT * HID];
__device__ __nv_bfloat16 g_wvdb[(size_t)VB * HID];
__device__ __nv_bfloat16 g_wvub[(size_t)HID * VB];
__device__ __nv_bfloat16 g_tb[(size_t)MAXTOK * VB];

extern __shared__ __align__(16) unsigned char dynsmem[];

__device__ __forceinline__ float gelu_tanh(float x) {
    float x3 = x * x * x;
    float t = tanhf(0.7978845608028654f * (x + 0.044715f * x3));
    return 0.5f * x * (1.0f + t);
}
__device__ __forceinline__ float sigmoidf(float x) {
    return 1.0f / (1.0f + expf(-x));
}

// ---------------- mma / cp.async helpers ----------------
__device__ __forceinline__ void ldsm4(unsigned r[4], unsigned addr) {
    asm volatile("ldmatrix.sync.aligned.m8n8.x4.shared.b16 {%0,%1,%2,%3}, [%4];"
                 : "=r"(r[0]), "=r"(r[1]), "=r"(r[2]), "=r"(r[3]) : "r"(addr));
}
__device__ __forceinline__ void mma16816(float c[4], const unsigned a[4], const unsigned b0, const unsigned b1) {
    asm("mma.sync.aligned.m16n8k16.row.col.f32.bf16.bf16.f32 "
        "{%0,%1,%2,%3}, {%4,%5,%6,%7}, {%8,%9}, {%0,%1,%2,%3};"
        : "+f"(c[0]), "+f"(c[1]), "+f"(c[2]), "+f"(c[3])
        : "r"(a[0]), "r"(a[1]), "r"(a[2]), "r"(a[3]), "r"(b0), "r"(b1));
}
__device__ __forceinline__ void cpasync16(unsigned saddr, const void* g) {
    asm volatile("cp.async.cg.shared.global [%0], [%1], 16;" :: "r"(saddr), "l"(g));
}
__device__ __forceinline__ void cpcommit() { asm volatile("cp.async.commit_group;"); }
__device__ __forceinline__ void cpwait2() { asm volatile("cp.async.wait_group 2;"); }

// 128x128 block tile, BK=32, 4-stage cp.async pipeline, 8 warps (2M x 4N).
__device__ __forceinline__ void gemm_tile_128x128(
    const __nv_bfloat16* __restrict__ A, const __nv_bfloat16* __restrict__ B,
    int kstride, int m0, int n0, int kbeg, int kend, float acc[4][4][4])
{
    __nv_bfloat16* As = (__nv_bfloat16*)dynsmem;
    __nv_bfloat16* Bs = As + STAGES * 128 * SMS;
    const int tid = threadIdx.x;
    const int lane = tid & 31, wid = tid >> 5;
    const int warp_m = wid & 1, warp_n = wid >> 1;

    const int lr = tid >> 2, lc = (tid & 3) << 3;
    const __nv_bfloat16* Ag0 = A + (size_t)(m0 + lr) * kstride + lc;
    const __nv_bfloat16* Ag1 = Ag0 + (size_t)64 * kstride;
    const __nv_bfloat16* Bg0 = B + (size_t)(n0 + lr) * kstride + lc;
    const __nv_bfloat16* Bg1 = Bg0 + (size_t)64 * kstride;

    const unsigned As_u = (unsigned)__cvta_generic_to_shared(As);
    const unsigned Bs_u = (unsigned)__cvta_generic_to_shared(Bs);
    const unsigned sa0 = As_u + (unsigned)((lr * SMS + lc) * 2);
    const unsigned sa1 = As_u + (unsigned)(((lr + 64) * SMS + lc) * 2);
    const unsigned sb0 = Bs_u + (unsigned)((lr * SMS + lc) * 2);
    const unsigned sb1 = Bs_u + (unsigned)(((lr + 64) * SMS + lc) * 2);

    const int lrow8 = (lane & 7) + ((lane >> 3) & 1) * 8;
    const int lcol8 = ((lane >> 4) & 1) * 8;
    const int arow = warp_m * 64 + lrow8;
    const int brow = warp_n * 32 + lrow8;

    const int NIT = (kend - kbeg) >> 5;

    #pragma unroll
    for (int s = 0; s < STAGES - 1; ++s) {
        unsigned so = s * STAGE_BYTES;
        int ko = kbeg + s * 32;
        cpasync16(sa0 + so, Ag0 + ko); cpasync16(sa1 + so, Ag1 + ko);
        cpasync16(sb0 + so, Bg0 + ko); cpasync16(sb1 + so, Bg1 + ko);
        cpcommit();
    }

    for (int kt = 0; kt < NIT; ++kt) {
        cpwait2();
        __syncthreads();
        int nxt = kt + STAGES - 1;
        if (nxt < NIT) {
            unsigned so = (nxt & (STAGES - 1)) * STAGE_BYTES;
            int ko = kbeg + nxt * 32;
            cpasync16(sa0 + so, Ag0 + ko); cpasync16(sa1 + so, Ag1 + ko);
            cpasync16(sb0 + so, Bg0 + ko); cpasync16(sb1 + so, Bg1 + ko);
        }
        cpcommit();
        unsigned cso = (kt & (STAGES - 1)) * STAGE_BYTES;
        #pragma unroll
        for (int k16 = 0; k16 < 2; ++k16) {
            unsigned af[4][4];
            #pragma unroll
            for (int mt = 0; mt < 4; ++mt)
                ldsm4(af[mt], As_u + cso + (unsigned)(((arow + mt * 16) * SMS + lcol8 + k16 * 16) * 2));
            unsigned bfr[2][4];
            #pragma unroll
            for (int nh = 0; nh < 2; ++nh)
                ldsm4(bfr[nh], Bs_u + cso + (unsigned)(((brow + nh * 16) * SMS + lcol8 + k16 * 16) * 2));
            #pragma unroll
            for (int mt = 0; mt < 4; ++mt)
                #pragma unroll
                for (int nt = 0; nt < 4; ++nt)
                    mma16816(acc[mt][nt], af[mt], bfr[nt >> 1][nt & 1], bfr[nt >> 1][2 + (nt & 1)]);
        }
    }
    __syncthreads();
}

// ---------------- zero scratch ----------------
__global__ void k_zero(int M) {
    int i = blockIdx.x * 256 + threadIdx.x;
    if (i < M) g_learned[i] = 0.0f;
    else if (i < M + NSLOT * VB) g_AV[i - M] = 0.0f;
}

// ---------------- convert weights to bf16 ----------------
__device__ __forceinline__ void cvt4(__nv_bfloat16* dst, int i4, const float* src) {
    float4 v = ((const float4*)src)[i4];
    __nv_bfloat162 p0, p1;
    p0.x = __float2bfloat16(v.x); p0.y = __float2bfloat16(v.y);
    p1.x = __float2bfloat16(v.z); p1.y = __float2bfloat16(v.w);
    ((__nv_bfloat162*)dst)[i4 * 2] = p0;
    ((__nv_bfloat162*)dst)[i4 * 2 + 1] = p1;
}
__global__ void k_cvt_all(const float* __restrict__ Wu1, const float* __restrict__ Wq,
                          const float* __restrict__ av, const float* __restrict__ wvd,
                          const float* __restrict__ wvu) {
    const int N_WU1 = 1024 * HID / 4, N_WQ = 64 * HID / 4, N_Z = 64 * HID / 4;
    const int N_AV = NSLOT * HID / 4, N_WVD = VB * HID / 4, N_WVU = HID * VB / 4;
    int i = blockIdx.x * 256 + threadIdx.x;
    if (i < N_WU1) { cvt4(g_wb, i, Wu1); return; }
    i -= N_WU1;
    if (i < N_WQ) { cvt4(g_wb + (size_t)1024 * HID, i, Wq); return; }
    i -= N_WQ;
    if (i < N_Z) {
        __nv_bfloat162 z; z.x = __float2bfloat16(0.f); z.y = z.x;
        ((__nv_bfloat162*)(g_wb + (size_t)1088 * HID))[i * 2] = z;
        ((__nv_bfloat162*)(g_wb + (size_t)1088 * HID))[i * 2 + 1] = z;
        return;
    }
    i -= N_Z;
    if (i < N_AV) { cvt4(g_avb, i, av); return; }
    i -= N_AV;
    if (i < N_WVD) { cvt4(g_wvdb, i, wvd); return; }
    i -= N_WVD;
    if (i < N_WVU) { cvt4(g_wvub, i, wvu); return; }
}

// ---------------- h: fp32 -> bf16 + per-row log-variance ----------------
__global__ __launch_bounds__(256) void k_prep_h(const float* __restrict__ h) {
    __shared__ float s_s[8], s_s2[8];
    int row = blockIdx.x, tid = threadIdx.x;
    const float* src = h + (size_t)row * HID;
    __nv_bfloat16* dst = g_hb + (size_t)row * HID;
    float s = 0.f, s2 = 0.f;
    #pragma unroll
    for (int i = 0; i < 4; i++) {
        int i4 = tid + 256 * i;
        float4 v = ((const float4*)src)[i4];
        s += v.x + v.y + v.z + v.w;
        s2 += v.x * v.x + v.y * v.y + v.z * v.z + v.w * v.w;
        __nv_bfloat162 p0, p1;
        p0.x = __float2bfloat16(v.x); p0.y = __float2bfloat16(v.y);
        p1.x = __float2bfloat16(v.z); p1.y = __float2bfloat16(v.w);
        ((__nv_bfloat162*)dst)[i4 * 2] = p0;
        ((__nv_bfloat162*)dst)[i4 * 2 + 1] = p1;
    }
    #pragma unroll
    for (int o = 16; o > 0; o >>= 1) {
        s += __shfl_xor_sync(0xFFFFFFFFu, s, o);
        s2 += __shfl_xor_sync(0xFFFFFFFFu, s2, o);
    }
    if ((tid & 31) == 0) { s_s[tid >> 5] = s; s_s2[tid >> 5] = s2; }
    __syncthreads();
    if (tid == 0) {
        float ts = 0.f, ts2 = 0.f;
        #pragma unroll
        for (int w = 0; w < 8; w++) { ts += s_s[w]; ts2 += s_s2[w]; }
        float mean = ts * (1.0f / HID);
        float var = ts2 * (1.0f / HID) - mean * mean;
        g_logvar[row] = log1pf(var);
    }
}

// ---------------- rk = aux_keys @ Wr^T  [NSLOT, RDIM] ----------------
__global__ __launch_bounds__(256) void k_rk(const float* __restrict__ aux_keys,
                                            const float* __restrict__ Wr) {
    __shared__ float sw[RDIM * BOT];
    __shared__ float sk[16 * BOT];
    int tid = threadIdx.x, s0 = blockIdx.x * 16;
    #pragma unroll
    for (int i = 0; i < 12; i++) sw[tid + 256 * i] = Wr[tid + 256 * i];
    #pragma unroll
    for (int i = 0; i < 4; i++) sk[tid + 256 * i] = aux_keys[s0 * BOT + tid + 256 * i];
    __syncthreads();
    #pragma unroll
    for (int i = 0; i < 3; i++) {
        int idx = tid + 256 * i;
        int s = idx / RDIM, r = idx - s * RDIM;
        float a = 0.f;
        #pragma unroll
        for (int j = 0; j < BOT; j++) a += sk[s * BOT + j] * sw[r * BOT + j];
        g_rk[(s0 + s) * RDIM + r] = a;
    }
}

// ---------------- AV = aux_values @ Wvd^T (bf16 mma, split-K=8) -------------
__global__ __launch_bounds__(256) void k_mma_av() {
    int m0 = blockIdx.y * 128, n0 = blockIdx.x * 128;
    int kbeg = blockIdx.z * 512;
    float acc[4][4][4] = {};
    gemm_tile_128x128(g_avb, g_wvdb, HID, m0, n0, kbeg, kbeg + 512, acc);
    int lane = threadIdx.x & 31, wid = threadIdx.x >> 5;
    int warp_m = wid & 1, warp_n = wid >> 1;
    int gID = lane >> 2, tig = lane & 3;
    #pragma unroll
    for (int mt = 0; mt < 4; ++mt)
        #pragma unroll
        for (int rh = 0; rh < 2; ++rh) {
            int m = m0 + warp_m * 64 + mt * 16 + gID + rh * 8;
            #pragma unroll
            for (int nt = 0; nt < 4; ++nt) {
                int n = n0 + warp_n * 32 + nt * 8 + tig * 2;
                atomicAdd(&g_AV[(size_t)m * VB + n], acc[mt][nt][rh * 2]);
                atomicAdd(&g_AV[(size_t)m * VB + n + 1], acc[mt][nt][rh * 2 + 1]);
            }
        }
}

// ------- combined learned + q GEMM: g_hb @ g_wb^T, N=1152 -------------------
__global__ __launch_bounds__(256) void k_mma_learn(const float* __restrict__ bu1,
                                                   const float* __restrict__ Wu2) {
    __shared__ float s_red[128];
    int m0 = blockIdx.y * 128, n0 = blockIdx.x * 128;
    float acc[4][4][4] = {};
    gemm_tile_128x128(g_hb, g_wb, HID, m0, n0, 0, HID, acc);
    int tid = threadIdx.x, lane = tid & 31, wid = tid >> 5;
    int warp_m = wid & 1, warp_n = wid >> 1;
    int gID = lane >> 2, tig = lane & 3;

    if (n0 < 1024) {
        if (tid < 128) s_red[tid] = 0.f;
        __syncthreads();
        #pragma unroll
        for (int mt = 0; mt < 4; ++mt)
            #pragma unroll
            for (int rh = 0; rh < 2; ++rh) {
                float p = 0.f;
                #pragma unroll
                for (int nt = 0; nt < 4; ++nt) {
                    int n = n0 + warp_n * 32 + nt * 8 + tig * 2;
                    float x0 = acc[mt][nt][rh * 2] + bu1[n];
                    float x1 = acc[mt][nt][rh * 2 + 1] + bu1[n + 1];
                    p += gelu_tanh(x0) * Wu2[n] + gelu_tanh(x1) * Wu2[n + 1];
                }
                p += __shfl_xor_sync(0xFFFFFFFFu, p, 1);
                p += __shfl_xor_sync(0xFFFFFFFFu, p, 2);
                if (tig == 0)
                    atomicAdd(&s_red[warp_m * 64 + mt * 16 + gID + rh * 8], p);
            }
        __syncthreads();
        if (tid < 128) atomicAdd(&g_learned[m0 + tid], s_red[tid]);
    } else {
        #pragma unroll
        for (int mt = 0; mt < 4; ++mt)
            #pragma unroll
            for (int rh = 0; rh < 2; ++rh) {
                int m = m0 + warp_m * 64 + mt * 16 + gID + rh * 8;
                #pragma unroll
                for (int nt = 0; nt < 4; ++nt) {
                    int nq = n0 + warp_n * 32 + nt * 8 + tig * 2 - 1024;
                    if (nq < 64) {
                        g_q[(size_t)m * BOT + nq] = acc[mt][nt][rh * 2];
                        g_q[(size_t)m * BOT + nq + 1] = acc[mt][nt][rh * 2 + 1];
                    }
                }
            }
    }
}

// ---------------- mean(log_var) ----------------
__global__ void k_mean(int M) {
    __shared__ float s[256];
    int tid = threadIdx.x;
    float a = 0.f;
    for (int i = tid; i < M; i += 256) a += g_logvar[i];
    s[tid] = a; __syncthreads();
    for (int st = 128; st > 0; st >>= 1) {
        if (tid < st) s[tid] += s[tid + st];
        __syncthreads();
    }
    if (tid == 0) g_meanlv = s[0] / (float)M;
}

// ------- scores[t,n] = (q_t @ Wr^T) . rk_n / sqrt(48) + log_rel[n] ----------
__global__ __launch_bounds__(256) void k_scores(const float* __restrict__ Wr,
                                                const float* __restrict__ log_rel) {
    __shared__ float sq[64 * 65];
    __shared__ float srq[64 * 49];
    __shared__ float srk[RDIM * BOT];
    int tid = threadIdx.x, t0 = blockIdx.x * 64;
    #pragma unroll
    for (int i = 0; i < 16; i++) {
        int idx = tid + 256 * i;
        int t = idx >> 6, c = idx & 63;
        sq[t * 65 + c] = g_q[(size_t)(t0 + t) * BOT + c];
    }
    #pragma unroll
    for (int i = 0; i < 12; i++) srk[tid + 256 * i] = Wr[tid + 256 * i];
    __syncthreads();
    #pragma unroll
    for (int i = 0; i < 12; i++) {
        int idx = tid + 256 * i;
        int t = idx / RDIM, r = idx - t * RDIM;
        float a = 0.f;
        #pragma unroll
        for (int j = 0; j < BOT; j++) a += sq[t * 65 + j] * srk[r * BOT + j];
        srq[t * 49 + r] = a;
    }
    __syncthreads();
    const float inv_sqrt_rdim = 0.14433756729740643f;
    for (int nt = 0; nt < 16; nt++) {
        __syncthreads();
        #pragma unroll
        for (int i = 0; i < 12; i++) {
            int idx = tid + 256 * i;
            srk[idx] = g_rk[(size_t)(nt * 64) * RDIM + idx];
        }
        __syncthreads();
        #pragma unroll
        for (int i = 0; i < 16; i++) {
            int idx = tid + 256 * i;
            int t = idx >> 6, s = idx & 63;
            float a = 0.f;
            #pragma unroll
            for (int r = 0; r < RDIM; r++) a += srq[t * 49 + r] * srk[s * RDIM + r];
            int n = nt * 64 + s;
            g_scores[(size_t)(t0 + t) * NSLOT + n] = a * inv_sqrt_rdim + log_rel[n];
        }
    }
}

// ------- topk: register-resident scores, warp-shuffle argmax ---------------
__global__ __launch_bounds__(256) void k_topk(const float* __restrict__ aux_keys,
                                              const float* __restrict__ log_rel) {
    __shared__ float s_q[BOT];
    __shared__ float s_wv[8];
    __shared__ int   s_wi[8];
    __shared__ int   s_win;
    __shared__ int   s_idx[TOPK];
    __shared__ float s_w[TOPK];
    __shared__ float s_attn[TOPK];

    int tok = blockIdx.x, tid = threadIdx.x;
    int lane = tid & 31, wrp = tid >> 5;
    if (tid < BOT) s_q[tid] = g_q[(size_t)tok * BOT + tid];

    // scores in registers: n = tid + 256*i
    float v[4];
    #pragma unroll
    for (int i = 0; i < 4; i++)
        v[i] = g_scores[(size_t)tok * NSLOT + tid + 256 * i];

    for (int kk = 0; kk < TOPK; kk++) {
        // thread-local argmax (ascending index scan, strict > keeps min index)
        float bv = v[0]; int bi = tid;
        #pragma unroll
        for (int i = 1; i < 4; i++) {
            if (v[i] > bv) { bv = v[i]; bi = tid + 256 * i; }
        }
        // warp argmax (tie-break: smaller index)
        #pragma unroll
        for (int o = 16; o > 0; o >>= 1) {
            float ov = __shfl_down_sync(0xFFFFFFFFu, bv, o);
            int oi = __shfl_down_sync(0xFFFFFFFFu, bi, o);
            if (ov > bv || (ov == bv && oi < bi)) { bv = ov; bi = oi; }
        }
        if (lane == 0) { s_wv[wrp] = bv; s_wi[wrp] = bi; }
        __syncthreads();
        if (tid == 0) {
            float fv = s_wv[0]; int fi = s_wi[0];
            #pragma unroll
            for (int w = 1; w < 8; w++) {
                float ov = s_wv[w]; int oi = s_wi[w];
                if (ov > fv || (ov == fv && oi < fi)) { fv = ov; fi = oi; }
            }
            s_idx[kk] = fi; s_win = fi;
        }
        __syncthreads();
        int win = s_win;
        if ((win & 255) == tid) v[win >> 8] = -INFINITY;
    }
    if (tid < TOPK) {
        int n = s_idx[tid];
        float a = 0.f;
        #pragma unroll
        for (int j = 0; j < BOT; j++) a += s_q[j] * aux_keys[n * BOT + j];
        s_attn[tid] = a * 0.125f + log_rel[n];
    }
    __syncthreads();
    if (tid == 0) {
        float mx = s_attn[0];
        #pragma unroll
        for (int k = 1; k < TOPK; k++) mx = fmaxf(mx, s_attn[k]);
        float sum = 0.f;
        #pragma unroll
        for (int k = 0; k < TOPK; k++) { float e = expf(s_attn[k] - mx); s_w[k] = e; sum += e; }
        float inv = 1.0f / sum;
        #pragma unroll
        for (int k = 0; k < TOPK; k++) s_w[k] *= inv;
    }
    __syncthreads();
    float acc = 0.f;
    #pragma unroll
    for (int k = 0; k < TOPK; k++) acc += s_w[k] * g_AV[(size_t)s_idx[k] * VB + tid];
    g_tb[(size_t)tok * VB + tid] = __float2bfloat16(acc);
}

// ------- final: out = h + gate * (t @ Wvu^T)  (bf16 mma, K=256) -------------
__global__ __launch_bounds__(256) void k_mma_fin(const float* __restrict__ hin,
                                                 float* __restrict__ out,
                                                 const float* __restrict__ bu2,
                                                 const float* __restrict__ gw1p,
                                                 const float* __restrict__ gbp) {
    int m0 = blockIdx.y * 128, n0 = blockIdx.x * 128;
    float acc[4][4][4] = {};
    gemm_tile_128x128(g_tb, g_wvub, VB, m0, n0, 0, VB, acc);
    int lane = threadIdx.x & 31, wid = threadIdx.x >> 5;
    int warp_m = wid & 1, warp_n = wid >> 1;
    int gID = lane >> 2, tig = lane & 3;
    float gw1 = *gw1p, gb = *gbp, b2 = *bu2, mlv = g_meanlv;
    #pragma unroll
    for (int mt = 0; mt < 4; ++mt)
        #pragma unroll
        for (int rh = 0; rh < 2; ++rh) {
            int m = m0 + warp_m * 64 + mt * 16 + gID + rh * 8;
            float nv = g_logvar[m] / (mlv + 1e-6f);
            float le = g_learned[m] + b2;
            float u = nv * 0.5f + sigmoidf(le) * 2.5f;
            u = fminf(fmaxf(u, 0.0f), 5.0f);
            float un = fminf(fmaxf((u - 0.5f) * (1.0f / 1.5f), 0.0f), 1.0f);
            float gate = sigmoidf(gw1 * un + gb);
            if (gate < 0.05f) gate = 0.0f;
            #pragma unroll
            for (int nt = 0; nt < 4; ++nt) {
                int n = n0 + warp_n * 32 + nt * 8 + tig * 2;
                size_t off = (size_t)m * HID + n;
                float2 h2 = *(const float2*)&hin[off];
                float2 o;
                o.x = h2.x + gate * acc[mt][nt][rh * 2];
                o.y = h2.y + gate * acc[mt][nt][rh * 2 + 1];
                *(float2*)&out[off] = o;
            }
        }
}

// ---------------------------------------------------------------------------
extern "C" void kernel_launch(void* const* d_in, const int* in_sizes, int n_in,
                              void* d_out, int out_size) {
    const float* h         = (const float*)d_in[0];
    const float* Wq        = (const float*)d_in[1];
    const float* Wr        = (const float*)d_in[2];
    const float* aux_keys  = (const float*)d_in[3];
    const float* aux_vals  = (const float*)d_in[4];
    const float* Wvd       = (const float*)d_in[5];
    const float* Wvu       = (const float*)d_in[6];
    const float* Wu1       = (const float*)d_in[7];
    const float* bu1       = (const float*)d_in[8];
    const float* Wu2       = (const float*)d_in[9];
    const float* bu2       = (const float*)d_in[10];
    const float* gate_w1   = (const float*)d_in[11];
    const float* gate_bias = (const float*)d_in[12];
    const float* log_rel   = (const float*)d_in[13];
    float* out = (float*)d_out;

    int M = in_sizes[0] / HID;
    if (M > MAXTOK) M = MAXTOK;

    static bool init_done = false;
    static cudaStream_t s1, s2;
    static cudaEvent_t evF, evH, evRK, evC, evAV;
    if (!init_done) {
        cudaFuncSetAttribute(k_mma_av,    cudaFuncAttributeMaxDynamicSharedMemorySize, SMEM_BYTES);
        cudaFuncSetAttribute(k_mma_learn, cudaFuncAttributeMaxDynamicSharedMemorySize, SMEM_BYTES);
        cudaFuncSetAttribute(k_mma_fin,   cudaFuncAttributeMaxDynamicSharedMemorySize, SMEM_BYTES);
        cudaStreamCreateWithFlags(&s1, cudaStreamNonBlocking);
        cudaStreamCreateWithFlags(&s2, cudaStreamNonBlocking);
        cudaEventCreateWithFlags(&evF,  cudaEventDisableTiming);
        cudaEventCreateWithFlags(&evH,  cudaEventDisableTiming);
        cudaEventCreateWithFlags(&evRK, cudaEventDisableTiming);
        cudaEventCreateWithFlags(&evC,  cudaEventDisableTiming);
        cudaEventCreateWithFlags(&evAV, cudaEventDisableTiming);
        init_done = true;
    }

    const int CVT_BLOCKS = (1024 * HID / 4 + 64 * HID / 4 + 64 * HID / 4 +
                            NSLOT * HID / 4 + VB * HID / 4 + HID * VB / 4 + 255) / 256;

    // fork point on the capture-origin (default) stream
    cudaEventRecord(evF, 0);

    // s1: h prep + mean(logvar)
    cudaStreamWaitEvent(s1, evF, 0);
    k_prep_h<<<M, 256, 0, s1>>>(h);
    k_mean<<<1, 256, 0, s1>>>(M);
    cudaEventRecord(evH, s1);

    // s2: rk, then AV GEMM (after weight cvt on stream0)
    cudaStreamWaitEvent(s2, evF, 0);
    k_rk<<<NSLOT / 16, 256, 0, s2>>>(aux_keys, Wr);
    cudaEventRecord(evRK, s2);

    // stream0: zero + weight conversion
    k_zero<<<(M + NSLOT * VB + 255) / 256, 256>>>(M);
    k_cvt_all<<<CVT_BLOCKS, 256>>>(Wu1, Wq, aux_vals, Wvd, Wvu);
    cudaEventRecord(evC, 0);

    // s2: AV = aux_values @ Wvd^T (needs cvt + zero)
    cudaStreamWaitEvent(s2, evC, 0);
    k_mma_av<<<dim3(VB / 128, NSLOT / 128, 8), 256, SMEM_BYTES, s2>>>();
    cudaEventRecord(evAV, s2);

    // stream0: learn GEMM (needs g_hb from s1 + g_wb from cvt)
    cudaStreamWaitEvent(0, evH, 0);
    k_mma_learn<<<dim3(NWB / 128, M / 128), 256, SMEM_BYTES>>>(bu1, Wu2);

    // stream0: scores (needs g_q from learn + g_rk from s2)
    cudaStreamWaitEvent(0, evRK, 0);
    k_scores<<<M / 64, 256>>>(Wr, log_rel);

    // stream0: topk (needs scores + g_AV from s2)
    cudaStreamWaitEvent(0, evAV, 0);
    k_topk<<<M, 256>>>(aux_keys, log_rel);

    // stream0: final
    k_mma_fin<<<dim3(HID / 128, M / 128), 256, SMEM_BYTES>>>(h, out, bu2, gate_w1, gate_bias);
}